// round 8
// baseline (speedup 1.0000x reference)
#include <cuda_runtime.h>
#include <math.h>

#define NT 2048      // B*T tokens
#define DD 128       // d_model
#define TT 512
#define BB 4
#define HH 8
#define EE 256
#define EPS 1e-6f
#define MAXB 4096    // bin capacity per expert (worst case)

// ---------------- scratch (device globals: allocation-free) ----------------
__device__ float g_q [NT*DD];
__device__ float g_k [NT*DD];
__device__ float g_v [NT*DD];
__device__ float g_ctxp [4*32*256];    // [part][bh][d*16+e]
__device__ float g_ksump[4*32*16];     // [part][bh][d]
__device__ float g_x2[NT*DD];
__device__ float g_h2[NT*DD];
__device__ float g_y [NT*256];         // [t][slot][128]
__device__ float g_ew[NT*2];
__device__ int   g_cnt[EE];
__device__ int   g_bin[EE*MAXB];       // packed t*2+slot
__device__ int   g_items[1024];        // (e<<16)|chunk
__device__ int   g_nitems;
__device__ int   g_done = 0;

// ---------------- helpers ----------------
__device__ __forceinline__ float warp_sum(float v){
#pragma unroll
    for (int o = 16; o > 0; o >>= 1) v += __shfl_xor_sync(0xffffffffu, v, o);
    return v;
}
__device__ __forceinline__ float warp_max(float v){
#pragma unroll
    for (int o = 16; o > 0; o >>= 1) v = fmaxf(v, __shfl_xor_sync(0xffffffffu, v, o));
    return v;
}
__device__ __forceinline__ float elu1(float z){ return z > 0.f ? z + 1.f : expf(z); }
__device__ __forceinline__ float silu(float g){ return g / (1.f + expf(-g)); }

// split-K half matmul, 8-token tile: acc[r] = sum_{i in [g*64,(g+1)*64)} aT[i][r]*W[i*128+o]
__device__ __forceinline__ void mm8h(const float* __restrict__ aT,
                                     const float* __restrict__ W,
                                     int o, int g, float acc[8]){
#pragma unroll
    for (int r = 0; r < 8; r++) acc[r] = 0.f;
    const float*  Wp = W + (size_t)(g*64)*128 + o;
    const float4* ap = (const float4*)(aT + (g*64)*8);
#pragma unroll 8
    for (int i = 0; i < 64; i++){
        float w = Wp[i*128];
        float4 a0 = ap[i*2+0], a1 = ap[i*2+1];
        acc[0]+=a0.x*w; acc[1]+=a0.y*w; acc[2]+=a0.z*w; acc[3]+=a0.w*w;
        acc[4]+=a1.x*w; acc[5]+=a1.y*w; acc[6]+=a1.z*w; acc[7]+=a1.w*w;
    }
}

__device__ __forceinline__ void mm8h_dual(const float* __restrict__ aT,
                                          const float* __restrict__ W1,
                                          const float* __restrict__ W2,
                                          int o, int g, float a1o[8], float a2o[8]){
#pragma unroll
    for (int r = 0; r < 8; r++){ a1o[r]=0.f; a2o[r]=0.f; }
    const float*  W1p = W1 + (size_t)(g*64)*128 + o;
    const float*  W2p = W2 + (size_t)(g*64)*128 + o;
    const float4* ap  = (const float4*)(aT + (g*64)*8);
#pragma unroll 8
    for (int i = 0; i < 64; i++){
        float w1 = W1p[i*128];
        float w2 = W2p[i*128];
        float4 a0 = ap[i*2+0], a1 = ap[i*2+1];
        a1o[0]+=a0.x*w1; a1o[1]+=a0.y*w1; a1o[2]+=a0.z*w1; a1o[3]+=a0.w*w1;
        a1o[4]+=a1.x*w1; a1o[5]+=a1.y*w1; a1o[6]+=a1.z*w1; a1o[7]+=a1.w*w1;
        a2o[0]+=a0.x*w2; a2o[1]+=a0.y*w2; a2o[2]+=a0.z*w2; a2o[3]+=a0.w*w2;
        a2o[4]+=a1.x*w2; a2o[5]+=a1.y*w2; a2o[6]+=a1.z*w2; a2o[7]+=a1.w*w2;
    }
}

// ---------------- K1: rmsnorm1 + q/kd/kv projections (8-token tile) ----------------
__global__ void k_pre(const float* __restrict__ x,   const float* __restrict__ g1,
                      const float* __restrict__ qW,  const float* __restrict__ qb,
                      const float* __restrict__ kdW, const float* __restrict__ kdb,
                      const float* __restrict__ kuW, const float* __restrict__ kub){
    __shared__ __align__(16) float aT [128*8];
    __shared__ __align__(16) float red[128*8];
    __shared__ __align__(16) float kdT[32*8];
    int tid = threadIdx.x;
    int c = tid & 127, g = tid >> 7;
    int w = tid >> 5,  l = tid & 31;
    int t0 = blockIdx.x*8;

    if (blockIdx.x == 0) g_cnt[tid & 255] = 0;

    // rmsnorm: warp w handles token w
    {
        int tok = w;
        const float* xr = x + (size_t)(t0+tok)*DD;
        float s = 0.f;
#pragma unroll
        for (int j = 0; j < 4; j++){ float v = xr[l+32*j]; s += v*v; }
        s = warp_sum(s);
        float rinv = rsqrtf(s*(1.f/128.f) + EPS);
#pragma unroll
        for (int j = 0; j < 4; j++){
            int i = l + 32*j;
            aT[i*8 + tok] = g1[i]*xr[i]*rinv;
        }
    }
    __syncthreads();

    // q = h1 @ qW + qb, elu+1   (split-K)
    {
        float acc[8];
        mm8h(aT, qW, c, g, acc);
        if (g){
#pragma unroll
            for (int r = 0; r < 8; r++) red[c*8+r] = acc[r];
        }
        __syncthreads();
        if (!g){
            float b = qb[c];
#pragma unroll
            for (int r = 0; r < 8; r++)
                g_q[(size_t)(t0+r)*DD + c] = elu1(acc[r] + red[c*8+r] + b);
        }
        __syncthreads();
    }

    // kd = h1 @ kdW + kdb  (32 outputs, split-K)
    {
        float acc[8];
#pragma unroll
        for (int r = 0; r < 8; r++) acc[r] = 0.f;
        if (c < 32){
            const float*  Wp = kdW + (size_t)(g*64)*32 + c;
            const float4* ap = (const float4*)(aT + (g*64)*8);
#pragma unroll 8
            for (int i = 0; i < 64; i++){
                float wv = Wp[i*32];
                float4 a0 = ap[i*2+0], a1 = ap[i*2+1];
                acc[0]+=a0.x*wv; acc[1]+=a0.y*wv; acc[2]+=a0.z*wv; acc[3]+=a0.w*wv;
                acc[4]+=a1.x*wv; acc[5]+=a1.y*wv; acc[6]+=a1.z*wv; acc[7]+=a1.w*wv;
            }
        }
        if (g && c < 32){
#pragma unroll
            for (int r = 0; r < 8; r++) red[c*8+r] = acc[r];
        }
        __syncthreads();
        if (!g && c < 32){
            float b = kdb[c];
#pragma unroll
            for (int r = 0; r < 8; r++) kdT[c*8+r] = acc[r] + red[c*8+r] + b;
        }
        __syncthreads();
    }

    // kv = kd @ kuW + kub : 256 outputs, one per thread, full K=32
    {
        int oo = tid;
        float acc[8];
#pragma unroll
        for (int r = 0; r < 8; r++) acc[r] = 0.f;
        const float*  Wp = kuW + oo;
        const float4* ap = (const float4*)kdT;
#pragma unroll 8
        for (int i = 0; i < 32; i++){
            float wv = Wp[i*256];
            float4 a0 = ap[i*2+0], a1 = ap[i*2+1];
            acc[0]+=a0.x*wv; acc[1]+=a0.y*wv; acc[2]+=a0.z*wv; acc[3]+=a0.w*wv;
            acc[4]+=a1.x*wv; acc[5]+=a1.y*wv; acc[6]+=a1.z*wv; acc[7]+=a1.w*wv;
        }
        int h = oo >> 5, p = oo & 31;
        float b = kub[oo];
#pragma unroll
        for (int r = 0; r < 8; r++){
            size_t t = t0 + r;
            float v = acc[r] + b;
            if (p < 16) g_k[t*DD + h*16 + p]        = elu1(v);
            else        g_v[t*DD + h*16 + (p-16)]   = v;
        }
    }
}

// ---------------- K2: partial context + ksum (4 T-partitions per (b,h)) ----------------
__global__ void k_ctx(){
    int bh = blockIdx.x >> 2, part = blockIdx.x & 3;
    int b = bh >> 3, h = bh & 7;
    int d = threadIdx.x >> 4, e = threadIdx.x & 15;
    const float* kp = g_k + ((size_t)(b*TT) + part*128)*DD + h*16 + d;
    const float* vp = g_v + ((size_t)(b*TT) + part*128)*DD + h*16 + e;
    float acc = 0.f, ks = 0.f;
#pragma unroll 8
    for (int t = 0; t < 128; t++){
        float kv_ = kp[t*DD];
        float vv  = vp[t*DD];
        acc += kv_ * vv;
        ks  += kv_;
    }
    g_ctxp[(part*32 + bh)*256 + d*16 + e] = acc;
    if (e == 0) g_ksump[(part*32 + bh)*16 + d] = ks;
}

// ---------------- top2 merge ----------------
__device__ __forceinline__ void top2_merge(float& v1, int& i1, float& v2, int& i2,
                                           float v, int i){
    if (v > v1 || (v == v1 && i < i1)){ v2 = v1; i2 = i1; v1 = v; i1 = i; }
    else if (v > v2 || (v == v2 && i < i2)){ v2 = v; i2 = i; }
}

// ---------------- K3: fused mid-section (8-token tile) + inline scheduler in last block ----------------
__global__ void k_fused(const float* __restrict__ oW,  const float* __restrict__ ob,
                        const float* __restrict__ rot, const float* __restrict__ tqs,
                        const float* __restrict__ s1W, const float* __restrict__ s1b,
                        const float* __restrict__ s2W, const float* __restrict__ s2b,
                        const float* __restrict__ x,   const float* __restrict__ g2,
                        const float* __restrict__ gateW, const float* __restrict__ gateb){
    __shared__ __align__(16) float u  [3072];  // ctx[2048]+q[1024]; later gate logits [8][256]
    __shared__ __align__(16) float tA [1024];
    __shared__ __align__(16) float tB [1024];
    __shared__ __align__(16) float red[1024];
    __shared__ float zsh[64], ksum_sh[128], mags[8], rinvs[8];
    __shared__ int   last_sh;
    __shared__ int   warp_tot[8];
    int tid = threadIdx.x;
    int c = tid & 127, g = tid >> 7;
    int w = tid >> 5,  l = tid & 31;
    int t0 = blockIdx.x*8, b = t0 >> 9;

    // load ctx (reduce 4 parts) and q tile
#pragma unroll
    for (int j = 0; j < 8; j++){
        int q = tid + 256*j;
        float s = 0.f;
#pragma unroll
        for (int p = 0; p < 4; p++) s += g_ctxp[p*8192 + b*2048 + q];
        u[q] = s;
    }
#pragma unroll
    for (int j = 0; j < 4; j++){
        int q = tid + 256*j;
        u[2048 + q] = g_q[(size_t)t0*DD + q];
    }
    if (!g){
        float s = 0.f;
#pragma unroll
        for (int p = 0; p < 4; p++) s += g_ksump[p*512 + b*128 + c];
        ksum_sh[c] = s;
    }
    __syncthreads();

    // z per (tok, head)
    if (tid < 64){
        int tok = tid >> 3, h = tid & 7;
        float s = 0.f;
#pragma unroll
        for (int d = 0; d < 16; d++) s += u[2048 + tok*128 + h*16 + d]*ksum_sh[h*16 + d];
        zsh[tid] = 1.f/(s + EPS);
    }
    __syncthreads();

    // attn: thread (c,g): col c, tokens g*4..g*4+3
    {
        int h = c >> 4, e = c & 15;
        float acc[4];
#pragma unroll
        for (int r = 0; r < 4; r++) acc[r] = 0.f;
#pragma unroll
        for (int d = 0; d < 16; d++){
            float cv = u[h*256 + d*16 + e];
#pragma unroll
            for (int r = 0; r < 4; r++) acc[r] += u[2048 + (g*4+r)*128 + h*16 + d]*cv;
        }
#pragma unroll
        for (int r = 0; r < 4; r++) tA[c*8 + g*4 + r] = acc[r]*zsh[(g*4+r)*8 + h];
    }
    __syncthreads();

    // oW: tA -> tB
    {
        float acc[8];
        mm8h(tA, oW, c, g, acc);
        if (g){
#pragma unroll
            for (int r = 0; r < 8; r++) red[c*8+r] = acc[r];
        }
        __syncthreads();
        if (!g){
            float bo = ob[c];
#pragma unroll
            for (int r = 0; r < 8; r++) tB[c*8+r] = acc[r] + red[c*8+r] + bo;
        }
        __syncthreads();
    }

    // rot: tB -> tA
    {
        float acc[8];
        mm8h(tB, rot, c, g, acc);
        if (g){
#pragma unroll
            for (int r = 0; r < 8; r++) red[c*8+r] = acc[r];
        }
        __syncthreads();
        if (!g){
#pragma unroll
            for (int r = 0; r < 8; r++) tA[c*8+r] = acc[r] + red[c*8+r];
        }
        __syncthreads();
    }

    // magnitudes per token (warp w -> token w)
    {
        float s = 0.f;
#pragma unroll
        for (int j = 0; j < 4; j++){ float v = tA[(l+32*j)*8 + w]; s += v*v; }
        s = warp_sum(s);
        if (l == 0) mags[w] = sqrtf(s*(1.f/128.f) + EPS);
    }
    __syncthreads();

    // turbo quant: tA -> tB
#pragma unroll
    for (int j = 0; j < 4; j++){
        int q = tid + 256*j;
        int r = q & 7, o = q >> 3;
        float m  = mags[r];
        float ph = tA[q]/m;
        ph = fminf(fmaxf(ph, -1.f), 1.f);
        tB[q] = ph*m*tqs[o];
    }
    __syncthreads();

    // swiglu(s1,s2) + residual -> x2 in tA + g_x2
    {
        float ag[8], au[8];
        mm8h_dual(tB, s1W, s2W, c, g, ag, au);
        if (g){
#pragma unroll
            for (int r = 0; r < 8; r++) red[c*8+r] = ag[r];
        }
        __syncthreads();
        if (!g){
#pragma unroll
            for (int r = 0; r < 8; r++) ag[r] += red[c*8+r];
        }
        __syncthreads();
        if (g){
#pragma unroll
            for (int r = 0; r < 8; r++) red[c*8+r] = au[r];
        }
        __syncthreads();
        if (!g){
            float b1 = s1b[c], b2 = s2b[c];
#pragma unroll
            for (int r = 0; r < 8; r++){
                float gg = ag[r] + b1;
                float uu = au[r] + red[c*8+r] + b2;
                float x2 = x[(size_t)(t0+r)*DD + c] + silu(gg)*uu;
                g_x2[(size_t)(t0+r)*DD + c] = x2;
                tA[c*8+r] = x2;
            }
        }
        __syncthreads();
    }

    // rmsnorm2 (warp w -> token w)
    {
        float s = 0.f;
#pragma unroll
        for (int j = 0; j < 4; j++){ float v = tA[(l+32*j)*8 + w]; s += v*v; }
        s = warp_sum(s);
        if (l == 0) rinvs[w] = rsqrtf(s*(1.f/128.f) + EPS);
    }
    __syncthreads();
    if (!g){
        float gg = g2[c];
#pragma unroll
        for (int r = 0; r < 8; r++){
            float h2 = gg * tA[c*8+r] * rinvs[r];
            g_h2[(size_t)(t0+r)*DD + c] = h2;
            tB[c*8+r] = h2;
        }
    }
    __syncthreads();

    // gate: 256 outputs, one per thread, full K=128
    {
        int oo = tid;
        float acc[8];
#pragma unroll
        for (int r = 0; r < 8; r++) acc[r] = 0.f;
        const float*  Wp = gateW + oo;
        const float4* ap = (const float4*)tB;
#pragma unroll 8
        for (int i = 0; i < 128; i++){
            float wv = Wp[i*256];
            float4 a0 = ap[i*2+0], a1 = ap[i*2+1];
            acc[0]+=a0.x*wv; acc[1]+=a0.y*wv; acc[2]+=a0.z*wv; acc[3]+=a0.w*wv;
            acc[4]+=a1.x*wv; acc[5]+=a1.y*wv; acc[6]+=a1.z*wv; acc[7]+=a1.w*wv;
        }
        float bb = gateb[oo];
#pragma unroll
        for (int r = 0; r < 8; r++) u[r*256 + oo] = acc[r] + bb;
    }
    __syncthreads();

    // softmax + top2 + binning: warp w -> token w
    {
        const float* row = u + w*256;
        float mx = -3.4e38f;
#pragma unroll
        for (int j = 0; j < 8; j++) mx = fmaxf(mx, row[l + 32*j]);
        mx = warp_max(mx);
        float sum = 0.f;
        float v1 = -3.4e38f, v2 = -3.4e38f; int i1 = 0x7fffffff, i2 = 0x7fffffff;
#pragma unroll
        for (int j = 0; j < 8; j++){
            int idx = l + 32*j;
            float v = row[idx];
            sum += expf(v - mx);
            top2_merge(v1, i1, v2, i2, v, idx);
        }
        sum = warp_sum(sum);
#pragma unroll
        for (int off = 16; off > 0; off >>= 1){
            float ov1 = __shfl_xor_sync(0xffffffffu, v1, off);
            int   oi1 = __shfl_xor_sync(0xffffffffu, i1, off);
            float ov2 = __shfl_xor_sync(0xffffffffu, v2, off);
            int   oi2 = __shfl_xor_sync(0xffffffffu, i2, off);
            top2_merge(v1, i1, v2, i2, ov1, oi1);
            top2_merge(v1, i1, v2, i2, ov2, oi2);
        }
        if (l == 0){
            int t = t0 + w;
            float p1 = expf(v1 - mx)/sum;
            float p2 = expf(v2 - mx)/sum;
            float den = p1 + p2 + EPS;
            g_ew[2*t]   = p1/den;
            g_ew[2*t+1] = p2/den;
            int s1 = atomicAdd(&g_cnt[i1], 1);
            g_bin[i1*MAXB + s1] = 2*t;
            int s2 = atomicAdd(&g_cnt[i2], 1);
            g_bin[i2*MAXB + s2] = 2*t + 1;
        }
    }

    // ---- inline scheduler: the last block to finish builds the work list ----
    __syncthreads();
    if (tid == 0){
        __threadfence();
        int d = atomicAdd(&g_done, 1);
        last_sh = (d == (int)gridDim.x - 1);
    }
    __syncthreads();
    if (last_sh){
        int e = tid;               // 256 threads -> 256 experts
        int n  = g_cnt[e];
        int ch = (n + 15) >> 4;
        int v = ch;
#pragma unroll
        for (int off = 1; off < 32; off <<= 1){
            int t = __shfl_up_sync(0xffffffffu, v, off);
            if (l >= off) v += t;
        }
        if (l == 31) warp_tot[w] = v;
        __syncthreads();
        int base = 0;
        for (int i = 0; i < w; i++) base += warp_tot[i];
        int excl = base + v - ch;
        for (int cc = 0; cc < ch; cc++) g_items[excl + cc] = (e << 16) | cc;
        if (e == 255){ g_nitems = excl + ch; g_done = 0; }
    }
}

// ---------------- K4: work-list expert matvecs, column-halved items ----------------
// block handles (item, half): 64 output columns (half*64..half*64+63), 4-way split-K (K=32 each)
__global__ void k_moe(const float* __restrict__ expW){
    __shared__ __align__(16) float hs [16*128];     // [r][i]
    __shared__ __align__(16) float red[3*16*64];    // [gk-1][r][o]
    __shared__ int toks[16];
    int tid = threadIdx.x;
    int o = tid & 63, gk = tid >> 6;   // o in [0,64), gk in [0,4)
    int total = g_nitems*2;
    for (int it = blockIdx.x; it < total; it += gridDim.x){
        int item = g_items[it >> 1];
        int half = it & 1;
        int e  = item >> 16;
        int c0 = (item & 0xffff) << 4;
        int n  = g_cnt[e];
        int m  = min(16, n - c0);
        if (tid < 16) toks[tid] = g_bin[e*MAXB + c0 + ((tid < m) ? tid : 0)];
        __syncthreads();
        // stage h tile [r][i], fully coalesced
#pragma unroll
        for (int j = 0; j < 8; j++){
            int idx = tid + 256*j;
            hs[idx] = g_h2[(size_t)(toks[idx >> 7] >> 1)*DD + (idx & 127)];
        }
        __syncthreads();
        // thread (o,gk): output col half*64+o, K rows [gk*32, gk*32+32)
        const float* Wp = expW + (size_t)e*16384 + (size_t)(gk*32)*128 + half*64 + o;
        float acc[16];
#pragma unroll
        for (int r = 0; r < 16; r++) acc[r] = 0.f;
#pragma unroll
        for (int i8 = 0; i8 < 4; i8++){
            float wv[8];
#pragma unroll
            for (int uu = 0; uu < 8; uu++) wv[uu] = Wp[(i8*8 + uu)*128];
#pragma unroll
            for (int r = 0; r < 16; r++){
                const float4* hp = (const float4*)(hs + r*128 + gk*32);
                float4 a0 = hp[i8*2+0], a1 = hp[i8*2+1];
                acc[r] += a0.x*wv[0] + a0.y*wv[1] + a0.z*wv[2] + a0.w*wv[3]
                        + a1.x*wv[4] + a1.y*wv[5] + a1.z*wv[6] + a1.w*wv[7];
            }
        }
        if (gk){
#pragma unroll
            for (int r = 0; r < 16; r++) red[(gk-1)*1024 + r*64 + o] = acc[r];
        }
        __syncthreads();
        if (!gk){
            for (int r = 0; r < m; r++){
                float s = acc[r] + red[r*64+o] + red[1024 + r*64+o] + red[2048 + r*64+o];
                int pk = toks[r];
                g_y[(size_t)(pk >> 1)*256 + (pk & 1)*128 + half*64 + o] = s;
            }
        }
        __syncthreads();
    }
}

// ---------------- K5: wavg -> swiglu(m1,m2) -> residual + consensus (8-token tile) ----------------
__global__ void k_moe_b(const float* __restrict__ m1W, const float* __restrict__ m1b,
                        const float* __restrict__ m2W, const float* __restrict__ m2b,
                        float* __restrict__ out, float* __restrict__ cons){
    __shared__ __align__(16) float aT [1024];
    __shared__ __align__(16) float red[1024];
    __shared__ float ews[16];
    int tid = threadIdx.x;
    int c = tid & 127, g = tid >> 7;
    int w = tid >> 5,  l = tid & 31;
    int t0 = blockIdx.x*8;

    if (tid < 16) ews[tid] = g_ew[t0*2 + tid];
#pragma unroll
    for (int j = 0; j < 4; j++){
        int q = tid + 256*j;
        int r = q & 7, o = q >> 3;
        size_t t = t0 + r;
        aT[q] = g_ew[2*t]*g_y[t*256 + o] + g_ew[2*t+1]*g_y[t*256 + 128 + o];
    }
    __syncthreads();

    float ag[8], au[8];
    mm8h_dual(aT, m1W, m2W, c, g, ag, au);
    if (g){
#pragma unroll
        for (int r = 0; r < 8; r++) red[c*8+r] = ag[r];
    }
    __syncthreads();
    if (!g){
#pragma unroll
        for (int r = 0; r < 8; r++) ag[r] += red[c*8+r];
    }
    __syncthreads();
    if (g){
#pragma unroll
        for (int r = 0; r < 8; r++) red[c*8+r] = au[r];
    }
    __syncthreads();
    if (!g){
        float b1 = m1b[c], b2 = m2b[c];
#pragma unroll
        for (int r = 0; r < 8; r++){
            size_t t = t0 + r;
            float gg = ag[r] + b1;
            float uu = au[r] + red[c*8+r] + b2;
            float ws = silu(gg)*uu;
            out[t*DD + c] = g_x2[t*DD + c] + ws;
            float w1 = ews[2*r], w2 = ews[2*r+1];
            float y1 = g_y[t*256 + c];
            float y2 = g_y[t*256 + 128 + c];
            float d1 = y1 - ws, d2 = y2 - ws;
            red[c*8+r] = w1*d1*d1 + w2*d2*d2;   // reuse red as wvar tile
        }
    }
    __syncthreads();

    // consensus: warp w -> token w
    {
        float s = 0.f;
#pragma unroll
        for (int j = 0; j < 4; j++) s += red[(l+32*j)*8 + w];
        s = warp_sum(s);
        if (l == 0) cons[t0 + w] = expf(-s*(1.f/128.f));
    }
}

// ---------------- launch ----------------
extern "C" void kernel_launch(void* const* d_in, const int* in_sizes, int n_in,
                              void* d_out, int out_size){
    const float* x    = (const float*)d_in[0];
    const float* g1   = (const float*)d_in[1];
    const float* qW   = (const float*)d_in[2];
    const float* qb   = (const float*)d_in[3];
    const float* kdW  = (const float*)d_in[4];
    const float* kdb  = (const float*)d_in[5];
    const float* kuW  = (const float*)d_in[6];
    const float* kub  = (const float*)d_in[7];
    const float* oW   = (const float*)d_in[8];
    const float* ob   = (const float*)d_in[9];
    const float* rot  = (const float*)d_in[10];
    const float* tqs  = (const float*)d_in[11];
    const float* s1W  = (const float*)d_in[12];
    const float* s1b  = (const float*)d_in[13];
    const float* s2W  = (const float*)d_in[14];
    const float* s2b  = (const float*)d_in[15];
    const float* g2   = (const float*)d_in[16];
    const float* gateW= (const float*)d_in[17];
    const float* gateb= (const float*)d_in[18];
    const float* expW = (const float*)d_in[19];
    const float* m1W  = (const float*)d_in[20];
    const float* m1b  = (const float*)d_in[21];
    const float* m2W  = (const float*)d_in[22];
    const float* m2b  = (const float*)d_in[23];

    float* out  = (float*)d_out;
    float* cons = out + (size_t)NT*DD;

    k_pre  <<<NT/8, 256>>>(x, g1, qW, qb, kdW, kdb, kuW, kub);
    k_ctx  <<<BB*HH*4, 256>>>();
    k_fused<<<NT/8, 256>>>(oW, ob, rot, tqs, s1W, s1b, s2W, s2b, x, g2, gateW, gateb);
    k_moe  <<<1024, 256>>>(expW);
    k_moe_b<<<NT/8, 256>>>(m1W, m1b, m2W, m2b, out, cons);
}

// round 9
// speedup vs baseline: 1.1241x; 1.1241x over previous
#include <cuda_runtime.h>
#include <math.h>

#define NT 2048      // B*T tokens
#define DD 128       // d_model
#define TT 512
#define BB 4
#define HH 8
#define EE 256
#define EPS 1e-6f
#define MAXB 4096

// ---------------- scratch ----------------
__device__ float g_q [NT*DD];
__device__ float g_k [NT*DD];
__device__ float g_v [NT*DD];
__device__ float g_ctxp [4*32*256];
__device__ float g_ksump[4*32*16];
__device__ float g_x2[NT*DD];
__device__ float g_h2[NT*DD];
__device__ float g_y [NT*256];
__device__ float g_ew[NT*2];
__device__ int   g_cnt[EE];
__device__ int   g_bin[EE*MAXB];
__device__ int   g_items[1024];
__device__ int   g_nitems;
__device__ int   g_done = 0;

// ---------------- helpers ----------------
__device__ __forceinline__ float warp_sum(float v){
#pragma unroll
    for (int o = 16; o > 0; o >>= 1) v += __shfl_xor_sync(0xffffffffu, v, o);
    return v;
}
__device__ __forceinline__ float warp_max(float v){
#pragma unroll
    for (int o = 16; o > 0; o >>= 1) v = fmaxf(v, __shfl_xor_sync(0xffffffffu, v, o));
    return v;
}
__device__ __forceinline__ float elu1(float z){ return z > 0.f ? z + 1.f : expf(z); }
__device__ __forceinline__ float silu(float g){ return g / (1.f + expf(-g)); }

// 2-col quarter-K matmul over 8-token tile: cols (oc, oc+64), K in [g4*32,(g4+1)*32)
__device__ __forceinline__ void mm8q(const float* __restrict__ aT,
                                     const float* __restrict__ W,
                                     int oc, int g4, float aA[8], float aB[8]){
#pragma unroll
    for (int r = 0; r < 8; r++){ aA[r]=0.f; aB[r]=0.f; }
    const float*  Wp = W + (size_t)(g4*32)*128 + oc;
    const float4* ap = (const float4*)(aT + (g4*32)*8);
#pragma unroll
    for (int i8 = 0; i8 < 4; i8++){
        float wA[8], wB[8];
#pragma unroll
        for (int u = 0; u < 8; u++){ int i=i8*8+u; wA[u]=Wp[i*128]; wB[u]=Wp[i*128+64]; }
#pragma unroll
        for (int u = 0; u < 8; u++){
            int i = i8*8+u;
            float4 a0 = ap[i*2+0], a1 = ap[i*2+1];
            aA[0]+=a0.x*wA[u]; aA[1]+=a0.y*wA[u]; aA[2]+=a0.z*wA[u]; aA[3]+=a0.w*wA[u];
            aA[4]+=a1.x*wA[u]; aA[5]+=a1.y*wA[u]; aA[6]+=a1.z*wA[u]; aA[7]+=a1.w*wA[u];
            aB[0]+=a0.x*wB[u]; aB[1]+=a0.y*wB[u]; aB[2]+=a0.z*wB[u]; aB[3]+=a0.w*wB[u];
            aB[4]+=a1.x*wB[u]; aB[5]+=a1.y*wB[u]; aB[6]+=a1.z*wB[u]; aB[7]+=a1.w*wB[u];
        }
    }
}

// dual-weight 2-col quarter-K (for swiglu pairs)
__device__ __forceinline__ void mm8q_dual(const float* __restrict__ aT,
                                          const float* __restrict__ W1,
                                          const float* __restrict__ W2,
                                          int oc, int g4,
                                          float gA[8], float gB[8],
                                          float uA[8], float uB[8]){
#pragma unroll
    for (int r = 0; r < 8; r++){ gA[r]=0.f; gB[r]=0.f; uA[r]=0.f; uB[r]=0.f; }
    const float*  W1p = W1 + (size_t)(g4*32)*128 + oc;
    const float*  W2p = W2 + (size_t)(g4*32)*128 + oc;
    const float4* ap  = (const float4*)(aT + (g4*32)*8);
#pragma unroll
    for (int i4 = 0; i4 < 8; i4++){
        float w1A[4], w1B[4], w2A[4], w2B[4];
#pragma unroll
        for (int u = 0; u < 4; u++){
            int i = i4*4+u;
            w1A[u]=W1p[i*128]; w1B[u]=W1p[i*128+64];
            w2A[u]=W2p[i*128]; w2B[u]=W2p[i*128+64];
        }
#pragma unroll
        for (int u = 0; u < 4; u++){
            int i = i4*4+u;
            float4 a0 = ap[i*2+0], a1 = ap[i*2+1];
            gA[0]+=a0.x*w1A[u]; gA[1]+=a0.y*w1A[u]; gA[2]+=a0.z*w1A[u]; gA[3]+=a0.w*w1A[u];
            gA[4]+=a1.x*w1A[u]; gA[5]+=a1.y*w1A[u]; gA[6]+=a1.z*w1A[u]; gA[7]+=a1.w*w1A[u];
            gB[0]+=a0.x*w1B[u]; gB[1]+=a0.y*w1B[u]; gB[2]+=a0.z*w1B[u]; gB[3]+=a0.w*w1B[u];
            gB[4]+=a1.x*w1B[u]; gB[5]+=a1.y*w1B[u]; gB[6]+=a1.z*w1B[u]; gB[7]+=a1.w*w1B[u];
            uA[0]+=a0.x*w2A[u]; uA[1]+=a0.y*w2A[u]; uA[2]+=a0.z*w2A[u]; uA[3]+=a0.w*w2A[u];
            uA[4]+=a1.x*w2A[u]; uA[5]+=a1.y*w2A[u]; uA[6]+=a1.z*w2A[u]; uA[7]+=a1.w*w2A[u];
            uB[0]+=a0.x*w2B[u]; uB[1]+=a0.y*w2B[u]; uB[2]+=a0.z*w2B[u]; uB[3]+=a0.w*w2B[u];
            uB[4]+=a1.x*w2B[u]; uB[5]+=a1.y*w2B[u]; uB[6]+=a1.z*w2B[u]; uB[7]+=a1.w*w2B[u];
        }
    }
}

// ---------------- K1: rmsnorm1 + q/kd/kv projections ----------------
__global__ void k_pre(const float* __restrict__ x,   const float* __restrict__ g1,
                      const float* __restrict__ qW,  const float* __restrict__ qb,
                      const float* __restrict__ kdW, const float* __restrict__ kdb,
                      const float* __restrict__ kuW, const float* __restrict__ kub){
    __shared__ __align__(16) float aT  [128*8];
    __shared__ __align__(16) float redq[3*1024];
    __shared__ __align__(16) float kdT [32*8];
    int tid = threadIdx.x;
    int c = tid & 127, g = tid >> 7;
    int oc = tid & 63, g4 = tid >> 6;
    int w = tid >> 5,  l = tid & 31;
    int t0 = blockIdx.x*8;

    if (blockIdx.x == 0) g_cnt[tid & 255] = 0;

    // rmsnorm: warp w -> token w
    {
        const float* xr = x + (size_t)(t0+w)*DD;
        float s = 0.f;
#pragma unroll
        for (int j = 0; j < 4; j++){ float v = xr[l+32*j]; s += v*v; }
        s = warp_sum(s);
        float rinv = rsqrtf(s*(1.f/128.f) + EPS);
#pragma unroll
        for (int j = 0; j < 4; j++){
            int i = l + 32*j;
            aT[i*8 + w] = g1[i]*xr[i]*rinv;
        }
    }
    __syncthreads();

    // q = h1 @ qW + qb, elu+1   (2-col quarter-K)
    {
        float aA[8], aB[8];
        mm8q(aT, qW, oc, g4, aA, aB);
        if (g4){
#pragma unroll
            for (int r = 0; r < 8; r++){
                redq[(g4-1)*1024 + r*128 + oc]      = aA[r];
                redq[(g4-1)*1024 + r*128 + oc + 64] = aB[r];
            }
        }
        __syncthreads();
        if (!g4){
            float bA = qb[oc], bB = qb[oc+64];
#pragma unroll
            for (int r = 0; r < 8; r++){
                size_t t = t0 + r;
                g_q[t*DD + oc]      = elu1(aA[r] + redq[r*128+oc] + redq[1024+r*128+oc] + redq[2048+r*128+oc] + bA);
                g_q[t*DD + oc + 64] = elu1(aB[r] + redq[r*128+oc+64] + redq[1024+r*128+oc+64] + redq[2048+r*128+oc+64] + bB);
            }
        }
        __syncthreads();
    }

    // kd = h1 @ kdW + kdb  (32 outputs, split-K halves)
    {
        float acc[8];
#pragma unroll
        for (int r = 0; r < 8; r++) acc[r] = 0.f;
        if (c < 32){
            const float*  Wp = kdW + (size_t)(g*64)*32 + c;
            const float4* ap = (const float4*)(aT + (g*64)*8);
#pragma unroll 8
            for (int i = 0; i < 64; i++){
                float wv = Wp[i*32];
                float4 a0 = ap[i*2+0], a1 = ap[i*2+1];
                acc[0]+=a0.x*wv; acc[1]+=a0.y*wv; acc[2]+=a0.z*wv; acc[3]+=a0.w*wv;
                acc[4]+=a1.x*wv; acc[5]+=a1.y*wv; acc[6]+=a1.z*wv; acc[7]+=a1.w*wv;
            }
        }
        if (g && c < 32){
#pragma unroll
            for (int r = 0; r < 8; r++) redq[c*8+r] = acc[r];
        }
        __syncthreads();
        if (!g && c < 32){
            float b = kdb[c];
#pragma unroll
            for (int r = 0; r < 8; r++) kdT[c*8+r] = acc[r] + redq[c*8+r] + b;
        }
        __syncthreads();
    }

    // kv = kd @ kuW + kub : 256 outputs, one per thread, K=32
    {
        int oo = tid;
        float acc[8];
#pragma unroll
        for (int r = 0; r < 8; r++) acc[r] = 0.f;
        const float*  Wp = kuW + oo;
        const float4* ap = (const float4*)kdT;
#pragma unroll 8
        for (int i = 0; i < 32; i++){
            float wv = Wp[i*256];
            float4 a0 = ap[i*2+0], a1 = ap[i*2+1];
            acc[0]+=a0.x*wv; acc[1]+=a0.y*wv; acc[2]+=a0.z*wv; acc[3]+=a0.w*wv;
            acc[4]+=a1.x*wv; acc[5]+=a1.y*wv; acc[6]+=a1.z*wv; acc[7]+=a1.w*wv;
        }
        int h = oo >> 5, p = oo & 31;
        float b = kub[oo];
#pragma unroll
        for (int r = 0; r < 8; r++){
            size_t t = t0 + r;
            float v = acc[r] + b;
            if (p < 16) g_k[t*DD + h*16 + p]      = elu1(v);
            else        g_v[t*DD + h*16 + (p-16)] = v;
        }
    }
}

// ---------------- K2: partial context + ksum ----------------
__global__ void k_ctx(){
    int bh = blockIdx.x >> 2, part = blockIdx.x & 3;
    int b = bh >> 3, h = bh & 7;
    int d = threadIdx.x >> 4, e = threadIdx.x & 15;
    const float* kp = g_k + ((size_t)(b*TT) + part*128)*DD + h*16 + d;
    const float* vp = g_v + ((size_t)(b*TT) + part*128)*DD + h*16 + e;
    float acc = 0.f, ks = 0.f;
#pragma unroll 8
    for (int t = 0; t < 128; t++){
        float kv_ = kp[t*DD];
        float vv  = vp[t*DD];
        acc += kv_ * vv;
        ks  += kv_;
    }
    g_ctxp[(part*32 + bh)*256 + d*16 + e] = acc;
    if (e == 0) g_ksump[(part*32 + bh)*16 + d] = ks;
}

// ---------------- top2 merge ----------------
__device__ __forceinline__ void top2_merge(float& v1, int& i1, float& v2, int& i2,
                                           float v, int i){
    if (v > v1 || (v == v1 && i < i1)){ v2 = v1; i2 = i1; v1 = v; i1 = i; }
    else if (v > v2 || (v == v2 && i < i2)){ v2 = v; i2 = i; }
}

// ---------------- K3: fused mid-section + inline scheduler ----------------
__global__ void k_fused(const float* __restrict__ oW,  const float* __restrict__ ob,
                        const float* __restrict__ rot, const float* __restrict__ tqs,
                        const float* __restrict__ s1W, const float* __restrict__ s1b,
                        const float* __restrict__ s2W, const float* __restrict__ s2b,
                        const float* __restrict__ x,   const float* __restrict__ g2,
                        const float* __restrict__ gateW, const float* __restrict__ gateb){
    __shared__ __align__(16) float u   [3072];
    __shared__ __align__(16) float tA  [1024];
    __shared__ __align__(16) float tB  [1024];
    __shared__ __align__(16) float redq[3*1024];
    __shared__ float zsh[64], ksum_sh[128], mags[8], rinvs[8];
    __shared__ int   last_sh;
    __shared__ int   warp_tot[8];
    int tid = threadIdx.x;
    int c = tid & 127, g = tid >> 7;
    int oc = tid & 63, g4 = tid >> 6;
    int w = tid >> 5,  l = tid & 31;
    int t0 = blockIdx.x*8, b = t0 >> 9;

    // load ctx (reduce 4 parts) and q tile
#pragma unroll
    for (int j = 0; j < 8; j++){
        int q = tid + 256*j;
        float s = 0.f;
#pragma unroll
        for (int p = 0; p < 4; p++) s += g_ctxp[p*8192 + b*2048 + q];
        u[q] = s;
    }
#pragma unroll
    for (int j = 0; j < 4; j++){
        int q = tid + 256*j;
        u[2048 + q] = g_q[(size_t)t0*DD + q];
    }
    if (!g){
        float s = 0.f;
#pragma unroll
        for (int p = 0; p < 4; p++) s += g_ksump[p*512 + b*128 + c];
        ksum_sh[c] = s;
    }
    __syncthreads();

    // z per (tok, head)
    if (tid < 64){
        int tok = tid >> 3, h = tid & 7;
        float s = 0.f;
#pragma unroll
        for (int d = 0; d < 16; d++) s += u[2048 + tok*128 + h*16 + d]*ksum_sh[h*16 + d];
        zsh[tid] = 1.f/(s + EPS);
    }
    __syncthreads();

    // attn
    {
        int h = c >> 4, e = c & 15;
        float acc[4];
#pragma unroll
        for (int r = 0; r < 4; r++) acc[r] = 0.f;
#pragma unroll
        for (int d = 0; d < 16; d++){
            float cv = u[h*256 + d*16 + e];
#pragma unroll
            for (int r = 0; r < 4; r++) acc[r] += u[2048 + (g*4+r)*128 + h*16 + d]*cv;
        }
#pragma unroll
        for (int r = 0; r < 4; r++) tA[c*8 + g*4 + r] = acc[r]*zsh[(g*4+r)*8 + h];
    }
    __syncthreads();

    // oW: tA -> tB
    {
        float aA[8], aB[8];
        mm8q(tA, oW, oc, g4, aA, aB);
        if (g4){
#pragma unroll
            for (int r = 0; r < 8; r++){
                redq[(g4-1)*1024 + r*128 + oc]      = aA[r];
                redq[(g4-1)*1024 + r*128 + oc + 64] = aB[r];
            }
        }
        __syncthreads();
        if (!g4){
            float bA = ob[oc], bB = ob[oc+64];
#pragma unroll
            for (int r = 0; r < 8; r++){
                tB[oc*8+r]      = aA[r] + redq[r*128+oc] + redq[1024+r*128+oc] + redq[2048+r*128+oc] + bA;
                tB[(oc+64)*8+r] = aB[r] + redq[r*128+oc+64] + redq[1024+r*128+oc+64] + redq[2048+r*128+oc+64] + bB;
            }
        }
        __syncthreads();
    }

    // rot: tB -> tA
    {
        float aA[8], aB[8];
        mm8q(tB, rot, oc, g4, aA, aB);
        if (g4){
#pragma unroll
            for (int r = 0; r < 8; r++){
                redq[(g4-1)*1024 + r*128 + oc]      = aA[r];
                redq[(g4-1)*1024 + r*128 + oc + 64] = aB[r];
            }
        }
        __syncthreads();
        if (!g4){
#pragma unroll
            for (int r = 0; r < 8; r++){
                tA[oc*8+r]      = aA[r] + redq[r*128+oc] + redq[1024+r*128+oc] + redq[2048+r*128+oc];
                tA[(oc+64)*8+r] = aB[r] + redq[r*128+oc+64] + redq[1024+r*128+oc+64] + redq[2048+r*128+oc+64];
            }
        }
        __syncthreads();
    }

    // magnitudes per token
    {
        float s = 0.f;
#pragma unroll
        for (int j = 0; j < 4; j++){ float v = tA[(l+32*j)*8 + w]; s += v*v; }
        s = warp_sum(s);
        if (l == 0) mags[w] = sqrtf(s*(1.f/128.f) + EPS);
    }
    __syncthreads();

    // turbo quant: tA -> tB
#pragma unroll
    for (int j = 0; j < 4; j++){
        int q = tid + 256*j;
        int r = q & 7, o = q >> 3;
        float m  = mags[r];
        float ph = tA[q]/m;
        ph = fminf(fmaxf(ph, -1.f), 1.f);
        tB[q] = ph*m*tqs[o];
    }
    __syncthreads();

    // swiglu(s1,s2) + residual -> x2 in tA + g_x2
    {
        float gA[8], gB[8], uA[8], uB[8];
        mm8q_dual(tB, s1W, s2W, oc, g4, gA, gB, uA, uB);
        if (g4){
#pragma unroll
            for (int r = 0; r < 8; r++){
                redq[(g4-1)*1024 + r*128 + oc]      = gA[r];
                redq[(g4-1)*1024 + r*128 + oc + 64] = gB[r];
            }
        }
        __syncthreads();
        if (!g4){
#pragma unroll
            for (int r = 0; r < 8; r++){
                gA[r] += redq[r*128+oc] + redq[1024+r*128+oc] + redq[2048+r*128+oc];
                gB[r] += redq[r*128+oc+64] + redq[1024+r*128+oc+64] + redq[2048+r*128+oc+64];
            }
        }
        __syncthreads();
        if (g4){
#pragma unroll
            for (int r = 0; r < 8; r++){
                redq[(g4-1)*1024 + r*128 + oc]      = uA[r];
                redq[(g4-1)*1024 + r*128 + oc + 64] = uB[r];
            }
        }
        __syncthreads();
        if (!g4){
            float b1A = s1b[oc], b1B = s1b[oc+64];
            float b2A = s2b[oc], b2B = s2b[oc+64];
#pragma unroll
            for (int r = 0; r < 8; r++){
                size_t t = t0 + r;
                float ggA = gA[r] + b1A;
                float uuA = uA[r] + redq[r*128+oc] + redq[1024+r*128+oc] + redq[2048+r*128+oc] + b2A;
                float x2A = x[t*DD + oc] + silu(ggA)*uuA;
                g_x2[t*DD + oc] = x2A;
                tA[oc*8+r] = x2A;
                float ggB = gB[r] + b1B;
                float uuB = uB[r] + redq[r*128+oc+64] + redq[1024+r*128+oc+64] + redq[2048+r*128+oc+64] + b2B;
                float x2B = x[t*DD + oc + 64] + silu(ggB)*uuB;
                g_x2[t*DD + oc + 64] = x2B;
                tA[(oc+64)*8+r] = x2B;
            }
        }
        __syncthreads();
    }

    // rmsnorm2
    {
        float s = 0.f;
#pragma unroll
        for (int j = 0; j < 4; j++){ float v = tA[(l+32*j)*8 + w]; s += v*v; }
        s = warp_sum(s);
        if (l == 0) rinvs[w] = rsqrtf(s*(1.f/128.f) + EPS);
    }
    __syncthreads();
    if (!g){
        float gg = g2[c];
#pragma unroll
        for (int r = 0; r < 8; r++){
            float h2 = gg * tA[c*8+r] * rinvs[r];
            g_h2[(size_t)(t0+r)*DD + c] = h2;
            tB[c*8+r] = h2;
        }
    }
    __syncthreads();

    // gate: thread (o2,g2h) -> outputs o2, o2+128 over K-half 64
    {
        int o2 = tid & 127, g2h = tid >> 7;
        float aA[8], aB[8];
#pragma unroll
        for (int r = 0; r < 8; r++){ aA[r]=0.f; aB[r]=0.f; }
        const float*  Wp = gateW + (size_t)(g2h*64)*256 + o2;
        const float4* ap = (const float4*)(tB + (g2h*64)*8);
#pragma unroll
        for (int i8 = 0; i8 < 8; i8++){
            float wA[8], wB[8];
#pragma unroll
            for (int uu2 = 0; uu2 < 8; uu2++){ int i=i8*8+uu2; wA[uu2]=Wp[i*256]; wB[uu2]=Wp[i*256+128]; }
#pragma unroll
            for (int uu2 = 0; uu2 < 8; uu2++){
                int i = i8*8+uu2;
                float4 a0 = ap[i*2+0], a1 = ap[i*2+1];
                aA[0]+=a0.x*wA[uu2]; aA[1]+=a0.y*wA[uu2]; aA[2]+=a0.z*wA[uu2]; aA[3]+=a0.w*wA[uu2];
                aA[4]+=a1.x*wA[uu2]; aA[5]+=a1.y*wA[uu2]; aA[6]+=a1.z*wA[uu2]; aA[7]+=a1.w*wA[uu2];
                aB[0]+=a0.x*wB[uu2]; aB[1]+=a0.y*wB[uu2]; aB[2]+=a0.z*wB[uu2]; aB[3]+=a0.w*wB[uu2];
                aB[4]+=a1.x*wB[uu2]; aB[5]+=a1.y*wB[uu2]; aB[6]+=a1.z*wB[uu2]; aB[7]+=a1.w*wB[uu2];
            }
        }
        if (g2h){
#pragma unroll
            for (int r = 0; r < 8; r++){
                redq[r*256 + o2]       = aA[r];
                redq[r*256 + 128 + o2] = aB[r];
            }
        }
        __syncthreads();
        if (!g2h){
            float bA = gateb[o2], bB = gateb[o2+128];
#pragma unroll
            for (int r = 0; r < 8; r++){
                u[r*256 + o2]       = aA[r] + redq[r*256 + o2] + bA;
                u[r*256 + 128 + o2] = aB[r] + redq[r*256 + 128 + o2] + bB;
            }
        }
        __syncthreads();
    }

    // softmax + top2 + binning: warp w -> token w
    {
        const float* row = u + w*256;
        float mx = -3.4e38f;
#pragma unroll
        for (int j = 0; j < 8; j++) mx = fmaxf(mx, row[l + 32*j]);
        mx = warp_max(mx);
        float sum = 0.f;
        float v1 = -3.4e38f, v2 = -3.4e38f; int i1 = 0x7fffffff, i2 = 0x7fffffff;
#pragma unroll
        for (int j = 0; j < 8; j++){
            int idx = l + 32*j;
            float v = row[idx];
            sum += expf(v - mx);
            top2_merge(v1, i1, v2, i2, v, idx);
        }
        sum = warp_sum(sum);
#pragma unroll
        for (int off = 16; off > 0; off >>= 1){
            float ov1 = __shfl_xor_sync(0xffffffffu, v1, off);
            int   oi1 = __shfl_xor_sync(0xffffffffu, i1, off);
            float ov2 = __shfl_xor_sync(0xffffffffu, v2, off);
            int   oi2 = __shfl_xor_sync(0xffffffffu, i2, off);
            top2_merge(v1, i1, v2, i2, ov1, oi1);
            top2_merge(v1, i1, v2, i2, ov2, oi2);
        }
        if (l == 0){
            int t = t0 + w;
            float p1 = expf(v1 - mx)/sum;
            float p2 = expf(v2 - mx)/sum;
            float den = p1 + p2 + EPS;
            g_ew[2*t]   = p1/den;
            g_ew[2*t+1] = p2/den;
            int s1 = atomicAdd(&g_cnt[i1], 1);
            g_bin[i1*MAXB + s1] = 2*t;
            int s2 = atomicAdd(&g_cnt[i2], 1);
            g_bin[i2*MAXB + s2] = 2*t + 1;
        }
    }

    // ---- inline scheduler: last block builds the work list ----
    __syncthreads();
    if (tid == 0){
        __threadfence();
        int d = atomicAdd(&g_done, 1);
        last_sh = (d == (int)gridDim.x - 1);
    }
    __syncthreads();
    if (last_sh){
        int e = tid;
        int n  = g_cnt[e];
        int ch = (n + 15) >> 4;
        int v = ch;
#pragma unroll
        for (int off = 1; off < 32; off <<= 1){
            int t = __shfl_up_sync(0xffffffffu, v, off);
            if (l >= off) v += t;
        }
        if (l == 31) warp_tot[w] = v;
        __syncthreads();
        int base = 0;
        for (int i = 0; i < w; i++) base += warp_tot[i];
        int excl = base + v - ch;
        for (int cc = 0; cc < ch; cc++) g_items[excl + cc] = (e << 16) | cc;
        if (e == 255){ g_nitems = excl + ch; g_done = 0; }
    }
}

// ---------------- K4: work-list expert matvecs (2 cols/thread, 4-way split-K) ----------------
__global__ void k_moe(const float* __restrict__ expW){
    __shared__ __align__(16) float hs  [16*128];     // 8KB
    __shared__ __align__(16) float redm[3*16*128];   // 24KB
    __shared__ int toks[16];
    int tid = threadIdx.x;
    int oc = tid & 63, g4 = tid >> 6;
    int n_items = g_nitems;
    for (int it = blockIdx.x; it < n_items; it += gridDim.x){
        int item = g_items[it];
        int e  = item >> 16;
        int c0 = (item & 0xffff) << 4;
        int n  = g_cnt[e];
        int m  = min(16, n - c0);
        if (tid < 16) toks[tid] = g_bin[e*MAXB + c0 + ((tid < m) ? tid : 0)];
        __syncthreads();
#pragma unroll
        for (int j = 0; j < 8; j++){
            int idx = tid + 256*j;
            hs[idx] = g_h2[(size_t)(toks[idx >> 7] >> 1)*DD + (idx & 127)];
        }
        __syncthreads();
        const float* Wp = expW + (size_t)e*16384 + (size_t)(g4*32)*128 + oc;
        float aA[16], aB[16];
#pragma unroll
        for (int r = 0; r < 16; r++){ aA[r]=0.f; aB[r]=0.f; }
#pragma unroll
        for (int i4 = 0; i4 < 8; i4++){
            float wA[4], wB[4];
#pragma unroll
            for (int u = 0; u < 4; u++){ int i=i4*4+u; wA[u]=Wp[i*128]; wB[u]=Wp[i*128+64]; }
#pragma unroll
            for (int r = 0; r < 16; r++){
                float4 a0 = ((const float4*)(hs + r*128 + g4*32))[i4];
                aA[r] += a0.x*wA[0] + a0.y*wA[1] + a0.z*wA[2] + a0.w*wA[3];
                aB[r] += a0.x*wB[0] + a0.y*wB[1] + a0.z*wB[2] + a0.w*wB[3];
            }
        }
        if (g4){
#pragma unroll
            for (int r = 0; r < 16; r++){
                redm[(g4-1)*2048 + r*128 + oc]      = aA[r];
                redm[(g4-1)*2048 + r*128 + oc + 64] = aB[r];
            }
        }
        __syncthreads();
        if (!g4){
            for (int r = 0; r < m; r++){
                int pk = toks[r];
                size_t base = (size_t)(pk >> 1)*256 + (pk & 1)*128;
                g_y[base + oc]      = aA[r] + redm[r*128+oc] + redm[2048+r*128+oc] + redm[4096+r*128+oc];
                g_y[base + oc + 64] = aB[r] + redm[r*128+oc+64] + redm[2048+r*128+oc+64] + redm[4096+r*128+oc+64];
            }
        }
        __syncthreads();
    }
}

// ---------------- K5: wavg -> swiglu(m1,m2) -> residual + consensus ----------------
__global__ void k_moe_b(const float* __restrict__ m1W, const float* __restrict__ m1b,
                        const float* __restrict__ m2W, const float* __restrict__ m2b,
                        float* __restrict__ out, float* __restrict__ cons){
    __shared__ __align__(16) float aT  [1024];
    __shared__ __align__(16) float redq[3*1024];
    __shared__ float ews[16];
    int tid = threadIdx.x;
    int oc = tid & 63, g4 = tid >> 6;
    int w = tid >> 5,  l = tid & 31;
    int t0 = blockIdx.x*8;

    if (tid < 16) ews[tid] = g_ew[t0*2 + tid];
#pragma unroll
    for (int j = 0; j < 4; j++){
        int q = tid + 256*j;
        int r = q & 7, o = q >> 3;
        size_t t = t0 + r;
        aT[q] = g_ew[2*t]*g_y[t*256 + o] + g_ew[2*t+1]*g_y[t*256 + 128 + o];
    }
    __syncthreads();

    float gA[8], gB[8], uA[8], uB[8];
    mm8q_dual(aT, m1W, m2W, oc, g4, gA, gB, uA, uB);
    if (g4){
#pragma unroll
        for (int r = 0; r < 8; r++){
            redq[(g4-1)*1024 + r*128 + oc]      = gA[r];
            redq[(g4-1)*1024 + r*128 + oc + 64] = gB[r];
        }
    }
    __syncthreads();
    if (!g4){
#pragma unroll
        for (int r = 0; r < 8; r++){
            gA[r] += redq[r*128+oc] + redq[1024+r*128+oc] + redq[2048+r*128+oc];
            gB[r] += redq[r*128+oc+64] + redq[1024+r*128+oc+64] + redq[2048+r*128+oc+64];
        }
    }
    __syncthreads();
    if (g4){
#pragma unroll
        for (int r = 0; r < 8; r++){
            redq[(g4-1)*1024 + r*128 + oc]      = uA[r];
            redq[(g4-1)*1024 + r*128 + oc + 64] = uB[r];
        }
    }
    __syncthreads();
    if (!g4){
        float b1A = m1b[oc], b1B = m1b[oc+64];
        float b2A = m2b[oc], b2B = m2b[oc+64];
#pragma unroll
        for (int r = 0; r < 8; r++){
            size_t t = t0 + r;
            float w1 = ews[2*r], w2 = ews[2*r+1];
            float ggA = gA[r] + b1A;
            float uuA = uA[r] + redq[r*128+oc] + redq[1024+r*128+oc] + redq[2048+r*128+oc] + b2A;
            float wsA = silu(ggA)*uuA;
            out[t*DD + oc] = g_x2[t*DD + oc] + wsA;
            float y1A = g_y[t*256 + oc], y2A = g_y[t*256 + 128 + oc];
            float d1A = y1A - wsA, d2A = y2A - wsA;
            aT[oc*8+r] = w1*d1A*d1A + w2*d2A*d2A;
            float ggB = gB[r] + b1B;
            float uuB = uB[r] + redq[r*128+oc+64] + redq[1024+r*128+oc+64] + redq[2048+r*128+oc+64] + b2B;
            float wsB = silu(ggB)*uuB;
            out[t*DD + oc + 64] = g_x2[t*DD + oc + 64] + wsB;
            float y1B = g_y[t*256 + oc + 64], y2B = g_y[t*256 + 128 + oc + 64];
            float d1B = y1B - wsB, d2B = y2B - wsB;
            aT[(oc+64)*8+r] = w1*d1B*d1B + w2*d2B*d2B;
        }
    }
    __syncthreads();

    // consensus: warp w -> token w (wvar tile now in aT)
    {
        float s = 0.f;
#pragma unroll
        for (int j = 0; j < 4; j++) s += aT[(l+32*j)*8 + w];
        s = warp_sum(s);
        if (l == 0) cons[t0 + w] = expf(-s*(1.f/128.f));
    }
}

// ---------------- launch ----------------
extern "C" void kernel_launch(void* const* d_in, const int* in_sizes, int n_in,
                              void* d_out, int out_size){
    const float* x    = (const float*)d_in[0];
    const float* g1   = (const float*)d_in[1];
    const float* qW   = (const float*)d_in[2];
    const float* qb   = (const float*)d_in[3];
    const float* kdW  = (const float*)d_in[4];
    const float* kdb  = (const float*)d_in[5];
    const float* kuW  = (const float*)d_in[6];
    const float* kub  = (const float*)d_in[7];
    const float* oW   = (const float*)d_in[8];
    const float* ob   = (const float*)d_in[9];
    const float* rot  = (const float*)d_in[10];
    const float* tqs  = (const float*)d_in[11];
    const float* s1W  = (const float*)d_in[12];
    const float* s1b  = (const float*)d_in[13];
    const float* s2W  = (const float*)d_in[14];
    const float* s2b  = (const float*)d_in[15];
    const float* g2   = (const float*)d_in[16];
    const float* gateW= (const float*)d_in[17];
    const float* gateb= (const float*)d_in[18];
    const float* expW = (const float*)d_in[19];
    const float* m1W  = (const float*)d_in[20];
    const float* m1b  = (const float*)d_in[21];
    const float* m2W  = (const float*)d_in[22];
    const float* m2b  = (const float*)d_in[23];

    float* out  = (float*)d_out;
    float* cons = out + (size_t)NT*DD;

    k_pre  <<<NT/8, 256>>>(x, g1, qW, qb, kdW, kdb, kuW, kub);
    k_ctx  <<<BB*HH*4, 256>>>();
    k_fused<<<NT/8, 256>>>(oW, ob, rot, tqs, s1W, s1b, s2W, s2b, x, g2, gateW, gateb);
    k_moe  <<<512, 256>>>(expW);
    k_moe_b<<<NT/8, 256>>>(m1W, m1b, m2W, m2b, out, cons);
}